// round 1
// baseline (speedup 1.0000x reference)
#include <cuda_runtime.h>

#define NNODES 100000
#define NEDGES 1600000
#define DIM 64
#define NEG_SLOPE 0.2f
#define EPS_IN 1e-5f

typedef unsigned long long u64;

// ---------------- scratch (static __device__, no allocations) ----------------
__device__ float g_xl[NNODES * DIM];
__device__ float g_xr[NNODES * DIM];
__device__ float g_h[NNODES * DIM];
__device__ float g_skip[NNODES * DIM];
__device__ float g_score[NEDGES];   // stored at CSR-sorted position
__device__ int   g_esrc[NEDGES];    // src at CSR-sorted position
__device__ int   g_epos[NEDGES];    // original edge -> sorted position
__device__ int   g_src[NEDGES];
__device__ int   g_dst[NEDGES];
__device__ int   g_deg[NNODES];
__device__ int   g_rowptr[NNODES + 1];
__device__ int   g_cursor[NNODES];
__device__ int   g_is64;

// ---------------- f32x2 packed helpers (sm_103a) ----------------
__device__ __forceinline__ u64 pack2(float x, float y) {
    u64 r; asm("mov.b64 %0, {%1, %2};" : "=l"(r) : "f"(x), "f"(y)); return r;
}
__device__ __forceinline__ void unpack2(u64 v, float& x, float& y) {
    asm("mov.b64 {%0, %1}, %2;" : "=f"(x), "=f"(y) : "l"(v));
}
__device__ __forceinline__ u64 ffma2(u64 a, u64 b, u64 c) {
    u64 d; asm("fma.rn.f32x2 %0, %1, %2, %3;" : "=l"(d) : "l"(a), "l"(b), "l"(c));
    return d;
}

// ---------------- edge index dtype detection + normalization ----------------
__global__ void detect_kernel(const int* w) {
    // int64 values < 2^31: every odd 32-bit word (high word) is 0.
    // int32 data: odd words are random node ids in [0, 100000) -> ~never all zero.
    if (threadIdx.x < 32) {
        int z = (w[2 * threadIdx.x + 1] == 0) ? 1 : 0;
        unsigned b = __ballot_sync(0xffffffffu, z != 0);
        if (threadIdx.x == 0) g_is64 = (b == 0xffffffffu) ? 1 : 0;
    }
}

__global__ void convert_kernel(const void* ei) {
    int e = blockIdx.x * blockDim.x + threadIdx.x;
    if (e >= NEDGES) return;
    if (g_is64) {
        const long long* p = (const long long*)ei;
        g_src[e] = (int)p[e];
        g_dst[e] = (int)p[NEDGES + e];
    } else {
        const int* p = (const int*)ei;
        g_src[e] = p[e];
        g_dst[e] = p[NEDGES + e];
    }
}

// ---------------- CSR build ----------------
__global__ void zero_deg_kernel() {
    int i = blockIdx.x * blockDim.x + threadIdx.x;
    if (i < NNODES) g_deg[i] = 0;
}

__global__ void count_kernel() {
    int e = blockIdx.x * blockDim.x + threadIdx.x;
    if (e < NEDGES) atomicAdd(&g_deg[g_dst[e]], 1);
}

__global__ void scan_kernel() {
    __shared__ int part[1024];
    int tid = threadIdx.x;
    const int chunk = (NNODES + 1023) / 1024;
    int start = tid * chunk;
    int end = start + chunk; if (end > NNODES) end = NNODES;
    int s = 0;
    for (int i = start; i < end; i++) s += g_deg[i];
    part[tid] = s;
    __syncthreads();
    for (int off = 1; off < 1024; off <<= 1) {
        int v = (tid >= off) ? part[tid - off] : 0;
        __syncthreads();
        part[tid] += v;
        __syncthreads();
    }
    int base = (tid == 0) ? 0 : part[tid - 1];
    for (int i = start; i < end; i++) {
        g_rowptr[i] = base;
        g_cursor[i] = base;
        base += g_deg[i];
    }
    if (tid == 1023) g_rowptr[NNODES] = base;  // == NEDGES
}

__global__ void place_kernel() {
    int e = blockIdx.x * blockDim.x + threadIdx.x;
    if (e >= NEDGES) return;
    int dst = g_dst[e];
    int pos = atomicAdd(&g_cursor[dst], 1);
    g_esrc[pos] = g_src[e];
    g_epos[e] = pos;
}

// ---------------- node linear: out[n,d] = b[d] + sum_k in[n,k] * W[d,k] ----------------
// warp per node; lane handles dims (l, l+32) via packed f32x2.
__global__ void linear_kernel(const float* xin,  // null -> use g_h
                              const float* __restrict__ W,
                              const float* __restrict__ b,
                              int outsel)        // 0=g_xl 1=g_xr 2=g_skip
{
    __shared__ u64 Wp[64][32];   // Wp[k][j] = (W[j][k], W[j+32][k])
    __shared__ u64 bp[32];
    __shared__ u64 xdup[8][64];
    const float* in = xin ? xin : g_h;
    float* out = (outsel == 0) ? g_xl : (outsel == 1) ? g_xr : g_skip;

    int tid = threadIdx.x;
    for (int i = tid; i < 2048; i += 256) {
        int k = i >> 5, j = i & 31;
        Wp[k][j] = pack2(W[j * 64 + k], W[(j + 32) * 64 + k]);
    }
    if (tid < 32) bp[tid] = pack2(b[tid], b[tid + 32]);
    __syncthreads();

    int w = tid >> 5, l = tid & 31;
    for (int n = blockIdx.x * 8 + w; n < NNODES; n += gridDim.x * 8) {
        float2 xv = ((const float2*)(in + (size_t)n * 64))[l];
        xdup[w][2 * l]     = pack2(xv.x, xv.x);
        xdup[w][2 * l + 1] = pack2(xv.y, xv.y);
        __syncwarp();
        u64 acc = bp[l];
        #pragma unroll 16
        for (int k = 0; k < 64; k++) acc = ffma2(xdup[w][k], Wp[k][l], acc);
        float a0, a1; unpack2(acc, a0, a1);
        out[(size_t)n * 64 + l]      = a0;
        out[(size_t)n * 64 + l + 32] = a1;
        __syncwarp();
    }
}

// ---------------- per-edge attention score ----------------
// warp per edge: m = xl[src] + xr[dst] + edge_attr@We^T ; score = dot(leakyrelu(m), att)
__global__ void score_kernel(const float* __restrict__ ea,
                             const float* __restrict__ We,
                             const float* __restrict__ att)
{
    __shared__ u64 Wp[64][32];
    __shared__ u64 ap[32];
    __shared__ u64 edup[8][64];
    int tid = threadIdx.x;
    for (int i = tid; i < 2048; i += 256) {
        int k = i >> 5, j = i & 31;
        Wp[k][j] = pack2(We[j * 64 + k], We[(j + 32) * 64 + k]);
    }
    if (tid < 32) ap[tid] = pack2(att[tid], att[tid + 32]);
    __syncthreads();

    int w = tid >> 5, l = tid & 31;
    for (int e = blockIdx.x * 8 + w; e < NEDGES; e += gridDim.x * 8) {
        int src = g_src[e];
        int dst = g_dst[e];
        float2 ev = ((const float2*)(ea + (size_t)e * 64))[l];
        edup[w][2 * l]     = pack2(ev.x, ev.x);
        edup[w][2 * l + 1] = pack2(ev.y, ev.y);
        u64 acc = pack2(g_xl[(size_t)src * 64 + l]      + g_xr[(size_t)dst * 64 + l],
                        g_xl[(size_t)src * 64 + l + 32] + g_xr[(size_t)dst * 64 + l + 32]);
        __syncwarp();
        #pragma unroll 16
        for (int k = 0; k < 64; k++) acc = ffma2(edup[w][k], Wp[k][l], acc);
        float m0, m1; unpack2(acc, m0, m1);
        float a0, a1; unpack2(ap[l], a0, a1);
        float v0 = (m0 > 0.f) ? m0 : NEG_SLOPE * m0;
        float v1 = (m1 > 0.f) ? m1 : NEG_SLOPE * m1;
        float s = v0 * a0 + v1 * a1;
        #pragma unroll
        for (int o = 16; o > 0; o >>= 1) s += __shfl_xor_sync(0xffffffffu, s, o);
        if (l == 0) g_score[g_epos[e]] = s;
        __syncwarp();
    }
}

// ---------------- per-node: softmax + weighted gather + bias/skip + relu + instnorm ----------------
// warp per node. out==null -> g_h ; useskip adds g_skip.
__global__ void aggregate_kernel(const float* __restrict__ bo,
                                 int useskip,
                                 float* out_ext)
{
    __shared__ float s_a[8][32];
    __shared__ int   s_s[8][32];
    float* out = out_ext ? out_ext : g_h;
    int tid = threadIdx.x;
    int w = tid >> 5, l = tid & 31;
    int n = blockIdx.x * 8 + w;
    if (n >= NNODES) return;

    int r0 = g_rowptr[n], r1 = g_rowptr[n + 1];

    float mx = -3.402823466e38f;
    for (int i = r0 + l; i < r1; i += 32) mx = fmaxf(mx, g_score[i]);
    #pragma unroll
    for (int o = 16; o > 0; o >>= 1) mx = fmaxf(mx, __shfl_xor_sync(0xffffffffu, mx, o));

    float ss = 0.f;
    for (int i = r0 + l; i < r1; i += 32) ss += __expf(g_score[i] - mx);
    #pragma unroll
    for (int o = 16; o > 0; o >>= 1) ss += __shfl_xor_sync(0xffffffffu, ss, o);
    float inv = 1.f / (ss + 1e-16f);

    float acc0 = 0.f, acc1 = 0.f;
    for (int c = r0; c < r1; c += 32) {
        int i = c + l;
        if (i < r1) {
            s_a[w][l] = __expf(g_score[i] - mx) * inv;
            s_s[w][l] = g_esrc[i];
        }
        __syncwarp();
        int cnt = r1 - c; if (cnt > 32) cnt = 32;
        for (int j = 0; j < cnt; j++) {
            float a = s_a[w][j];
            const float* xs = g_xl + (size_t)s_s[w][j] * 64;
            acc0 += a * xs[l];
            acc1 += a * xs[l + 32];
        }
        __syncwarp();
    }

    float v0 = acc0 + bo[l];
    float v1 = acc1 + bo[l + 32];
    if (useskip) {
        v0 += g_skip[(size_t)n * 64 + l];
        v1 += g_skip[(size_t)n * 64 + l + 32];
    }
    v0 = fmaxf(v0, 0.f);
    v1 = fmaxf(v1, 0.f);

    float t = v0 + v1;
    #pragma unroll
    for (int o = 16; o > 0; o >>= 1) t += __shfl_xor_sync(0xffffffffu, t, o);
    float mu = t * (1.f / 64.f);
    float d0 = v0 - mu, d1 = v1 - mu;
    float q = d0 * d0 + d1 * d1;
    #pragma unroll
    for (int o = 16; o > 0; o >>= 1) q += __shfl_xor_sync(0xffffffffu, q, o);
    float sc = rsqrtf(q * (1.f / 64.f) + EPS_IN);

    out[(size_t)n * 64 + l]      = d0 * sc;
    out[(size_t)n * 64 + l + 32] = d1 * sc;
}

// ---------------- launch ----------------
extern "C" void kernel_launch(void* const* d_in, const int* in_sizes, int n_in,
                              void* d_out, int out_size) {
    const float* x     = (const float*)d_in[0];
    const void*  ei    = d_in[1];
    const float* ea    = (const float*)d_in[2];
    const float* Wl1   = (const float*)d_in[3];
    const float* bl1   = (const float*)d_in[4];
    const float* Wr1   = (const float*)d_in[5];
    const float* br1   = (const float*)d_in[6];
    const float* We1   = (const float*)d_in[7];
    const float* att1  = (const float*)d_in[8];
    const float* bo1   = (const float*)d_in[9];
    const float* Wl2   = (const float*)d_in[10];
    const float* bl2   = (const float*)d_in[11];
    const float* Wr2   = (const float*)d_in[12];
    const float* br2   = (const float*)d_in[13];
    const float* We2   = (const float*)d_in[14];
    const float* att2  = (const float*)d_in[15];
    const float* bo2   = (const float*)d_in[16];
    const float* Wskip = (const float*)d_in[17];
    const float* bskip = (const float*)d_in[18];
    float* out = (float*)d_out;

    const int EB = (NEDGES + 255) / 256;
    const int NB = (NNODES + 255) / 256;

    // edge index normalization + CSR build (once per launch, reused by both layers)
    detect_kernel<<<1, 32>>>((const int*)ei);
    convert_kernel<<<EB, 256>>>(ei);
    zero_deg_kernel<<<NB, 256>>>();
    count_kernel<<<EB, 256>>>();
    scan_kernel<<<1, 1024>>>();
    place_kernel<<<EB, 256>>>();

    // ----- layer 1 -----
    linear_kernel<<<1184, 256>>>(x, Wl1, bl1, 0);   // g_xl
    linear_kernel<<<1184, 256>>>(x, Wr1, br1, 1);   // g_xr
    linear_kernel<<<1184, 256>>>(x, Wskip, bskip, 2); // g_skip
    score_kernel<<<4096, 256>>>(ea, We1, att1);
    aggregate_kernel<<<(NNODES + 7) / 8, 256>>>(bo1, 0, nullptr);  // -> g_h

    // ----- layer 2 -----
    linear_kernel<<<1184, 256>>>(nullptr, Wl2, bl2, 0);  // g_xl = h@Wl2^T+bl2
    linear_kernel<<<1184, 256>>>(nullptr, Wr2, br2, 1);  // g_xr
    score_kernel<<<4096, 256>>>(ea, We2, att2);
    aggregate_kernel<<<(NNODES + 7) / 8, 256>>>(bo2, 1, out);      // -> d_out
}

// round 3
// speedup vs baseline: 1.3888x; 1.3888x over previous
#include <cuda_runtime.h>

#define NNODES 100000
#define NEDGES 1600000
#define NEG_SLOPE 0.2f
#define EPS_IN 1e-5f

typedef unsigned long long u64;

// ---------------- scratch ----------------
__device__ float g_xl[NNODES * 64];
__device__ float g_xr[NNODES * 64];
__device__ float g_h[NNODES * 64];
__device__ float g_skip[NNODES * 64];
__device__ float g_score[NEDGES];   // CSR-sorted order
__device__ int   g_esrc[NEDGES];    // src at sorted pos
__device__ int   g_edsts[NEDGES];   // dst at sorted pos
__device__ int   g_eorig[NEDGES];   // sorted pos -> original edge id
__device__ int   g_src[NEDGES];
__device__ int   g_dst[NEDGES];
__device__ int   g_deg[NNODES];
__device__ int   g_rowptr[NNODES + 1];
__device__ int   g_cursor[NNODES];
__device__ int   g_is64;

// ---------------- f32x2 helpers ----------------
__device__ __forceinline__ u64 pack2(float x, float y) {
    u64 r; asm("mov.b64 %0, {%1, %2};" : "=l"(r) : "f"(x), "f"(y)); return r;
}
__device__ __forceinline__ void unpack2(u64 v, float& x, float& y) {
    asm("mov.b64 {%0, %1}, %2;" : "=f"(x), "=f"(y) : "l"(v));
}
__device__ __forceinline__ u64 ffma2(u64 a, u64 b, u64 c) {
    u64 d; asm("fma.rn.f32x2 %0, %1, %2, %3;" : "=l"(d) : "l"(a), "l"(b), "l"(c));
    return d;
}

// ---------------- edge index dtype detect + convert ----------------
__global__ void detect_kernel(const int* w) {
    if (threadIdx.x < 32) {
        int z = (w[2 * threadIdx.x + 1] == 0) ? 1 : 0;
        unsigned b = __ballot_sync(0xffffffffu, z != 0);
        if (threadIdx.x == 0) g_is64 = (b == 0xffffffffu) ? 1 : 0;
    }
}

__global__ void convert_kernel(const void* ei) {
    int e = blockIdx.x * blockDim.x + threadIdx.x;
    if (e >= NEDGES) return;
    if (g_is64) {
        const long long* p = (const long long*)ei;
        g_src[e] = (int)p[e];
        g_dst[e] = (int)p[NEDGES + e];
    } else {
        const int* p = (const int*)ei;
        g_src[e] = p[e];
        g_dst[e] = p[NEDGES + e];
    }
}

// ---------------- CSR build ----------------
__global__ void zero_deg_kernel() {
    int i = blockIdx.x * blockDim.x + threadIdx.x;
    if (i < NNODES) g_deg[i] = 0;
}

__global__ void count_kernel() {
    int e = blockIdx.x * blockDim.x + threadIdx.x;
    if (e < NEDGES) atomicAdd(&g_deg[g_dst[e]], 1);
}

__global__ void scan_kernel() {
    __shared__ int part[1024];
    int tid = threadIdx.x;
    const int chunk = (NNODES + 1023) / 1024;
    int start = tid * chunk;
    int end = start + chunk; if (end > NNODES) end = NNODES;
    int s = 0;
    for (int i = start; i < end; i++) s += g_deg[i];
    part[tid] = s;
    __syncthreads();
    for (int off = 1; off < 1024; off <<= 1) {
        int v = (tid >= off) ? part[tid - off] : 0;
        __syncthreads();
        part[tid] += v;
        __syncthreads();
    }
    int base = (tid == 0) ? 0 : part[tid - 1];
    for (int i = start; i < end; i++) {
        g_rowptr[i] = base;
        g_cursor[i] = base;
        base += g_deg[i];
    }
    if (tid == 1023) g_rowptr[NNODES] = base;
}

__global__ void place_kernel() {
    int e = blockIdx.x * blockDim.x + threadIdx.x;
    if (e >= NEDGES) return;
    int dst = g_dst[e];
    int pos = atomicAdd(&g_cursor[dst], 1);
    g_esrc[pos] = g_src[e];
    g_edsts[pos] = dst;
    g_eorig[pos] = e;
}

// ---------------- block-tiled GEMM: rows x 64, K=64 ----------------
// MODE 0 (linear): O[r] = A[r] @ W^T + vb     (A row = input row r)
// MODE 1 (score):  m = xl[src]+xr[dst] + ea[orig] @ W^T ; g_score[r] = lrelu(m).vb
// Tile: 128 rows x 64 cols. 256 threads; thread(lane,wid): rows {lane,lane+32,lane+64,lane+96},
// cols wid*8..wid*8+7 as 4 f32x2 col-pairs.
#define SMEM_FLOATS (64*132 + 64*68 + 128*68 + 128*9 + 64)
#define SMEM_BYTES  (SMEM_FLOATS * 4)

template<int MODE>
__global__ void __launch_bounds__(256, 2) gemm_kernel(
    const float* Aext, const float* __restrict__ W,
    const float* __restrict__ vb, float* Oext,
    int asel, int osel, int nrows)
{
    extern __shared__ __align__(16) float sm[];
    float* a_s  = sm;                  // [64][132] transposed A tile
    float* w_s  = sm + 64 * 132;       // [64][68]  w_s[k][d] = W[d][k]
    float* m_s  = w_s + 64 * 68;       // [128][68] init values (MODE 1)
    float* sp   = m_s + 128 * 68;      // [128][9]  partial scores
    float* vb_s = sp + 128 * 9;        // [64]      bias or att

    const float* A = (asel == 1) ? g_h : Aext;
    float* O = (osel == 0) ? g_xl : (osel == 1) ? g_xr : (osel == 2) ? g_skip : Oext;

    int tid = threadIdx.x;
    int lane = tid & 31, wid = tid >> 5;
    int r0 = blockIdx.x * 128;

    // stage W transposed
    for (int i = tid; i < 1024; i += 256) {
        int d = i >> 4, j = i & 15;
        float4 v = *(const float4*)(W + d * 64 + j * 4);
        w_s[(4 * j + 0) * 68 + d] = v.x;
        w_s[(4 * j + 1) * 68 + d] = v.y;
        w_s[(4 * j + 2) * 68 + d] = v.z;
        w_s[(4 * j + 3) * 68 + d] = v.w;
    }
    if (tid < 64) vb_s[tid] = vb[tid];

    // stage A transposed: a_s[k][r_local]; iter covers 4 rows x 16 k
    for (int it = wid; it < 128; it += 8) {
        int q = it & 31, gch = it >> 5;
        int rl = q * 4 + (lane & 3);
        int rr = r0 + rl;
        int orig;
        if (MODE == 1) orig = g_eorig[rr];
        else orig = (rr < nrows) ? rr : 0;
        int k = gch * 16 + 2 * (lane >> 2);
        float2 v = *(const float2*)(A + (size_t)orig * 64 + k);
        a_s[k * 132 + rl]       = v.x;
        a_s[(k + 1) * 132 + rl] = v.y;
    }

    if (MODE == 1) {
        // stage init: m_s[r] = xl[src] + xr[dst]  (dst nearly sorted -> L1 reuse)
        for (int r = wid; r < 128; r += 8) {
            int rr = r0 + r;
            int s = g_esrc[rr], dd = g_edsts[rr];
            float2 va = *(const float2*)(g_xl + (size_t)s * 64 + 2 * lane);
            float2 vc = *(const float2*)(g_xr + (size_t)dd * 64 + 2 * lane);
            float2 o; o.x = va.x + vc.x; o.y = va.y + vc.y;
            *(float2*)(m_s + r * 68 + 2 * lane) = o;
        }
    }
    __syncthreads();

    u64 acc[4][4];
    if (MODE == 1) {
        #pragma unroll
        for (int i = 0; i < 4; i++) {
            const u64* mp = (const u64*)(m_s + (lane + 32 * i) * 68 + wid * 8);
            #pragma unroll
            for (int p = 0; p < 4; p++) acc[i][p] = mp[p];
        }
    } else {
        #pragma unroll
        for (int p = 0; p < 4; p++) {
            u64 bv = *(const u64*)(vb_s + wid * 8 + 2 * p);
            #pragma unroll
            for (int i = 0; i < 4; i++) acc[i][p] = bv;
        }
    }

    #pragma unroll 4
    for (int k = 0; k < 64; k++) {
        const float* ar = a_s + k * 132 + lane;
        float a0 = ar[0], a1 = ar[32], a2 = ar[64], a3 = ar[96];
        const ulonglong2* bw = (const ulonglong2*)(w_s + k * 68 + wid * 8);
        ulonglong2 bA = bw[0], bB = bw[1];
        u64 d0 = pack2(a0, a0), d1 = pack2(a1, a1), d2 = pack2(a2, a2), d3 = pack2(a3, a3);
        acc[0][0] = ffma2(d0, bA.x, acc[0][0]); acc[0][1] = ffma2(d0, bA.y, acc[0][1]);
        acc[0][2] = ffma2(d0, bB.x, acc[0][2]); acc[0][3] = ffma2(d0, bB.y, acc[0][3]);
        acc[1][0] = ffma2(d1, bA.x, acc[1][0]); acc[1][1] = ffma2(d1, bA.y, acc[1][1]);
        acc[1][2] = ffma2(d1, bB.x, acc[1][2]); acc[1][3] = ffma2(d1, bB.y, acc[1][3]);
        acc[2][0] = ffma2(d2, bA.x, acc[2][0]); acc[2][1] = ffma2(d2, bA.y, acc[2][1]);
        acc[2][2] = ffma2(d2, bB.x, acc[2][2]); acc[2][3] = ffma2(d2, bB.y, acc[2][3]);
        acc[3][0] = ffma2(d3, bA.x, acc[3][0]); acc[3][1] = ffma2(d3, bA.y, acc[3][1]);
        acc[3][2] = ffma2(d3, bB.x, acc[3][2]); acc[3][3] = ffma2(d3, bB.y, acc[3][3]);
    }

    if (MODE == 1) {
        #pragma unroll
        for (int i = 0; i < 4; i++) {
            float s = 0.f;
            #pragma unroll
            for (int p = 0; p < 4; p++) {
                float x0, x1; unpack2(acc[i][p], x0, x1);
                float t0 = (x0 > 0.f) ? x0 : NEG_SLOPE * x0;
                float t1 = (x1 > 0.f) ? x1 : NEG_SLOPE * x1;
                s += t0 * vb_s[wid * 8 + 2 * p] + t1 * vb_s[wid * 8 + 2 * p + 1];
            }
            sp[(lane + 32 * i) * 9 + wid] = s;
        }
        __syncthreads();
        if (tid < 128) {
            float s = 0.f;
            #pragma unroll
            for (int w = 0; w < 8; w++) s += sp[tid * 9 + w];
            g_score[r0 + tid] = s;   // contiguous, already CSR-sorted
        }
    } else {
        #pragma unroll
        for (int i = 0; i < 4; i++) {
            int rr = r0 + lane + 32 * i;
            if (rr < nrows) {
                float v0, v1, v2, v3, v4, v5, v6, v7;
                unpack2(acc[i][0], v0, v1); unpack2(acc[i][1], v2, v3);
                unpack2(acc[i][2], v4, v5); unpack2(acc[i][3], v6, v7);
                *(float4*)(O + (size_t)rr * 64 + wid * 8)     = make_float4(v0, v1, v2, v3);
                *(float4*)(O + (size_t)rr * 64 + wid * 8 + 4) = make_float4(v4, v5, v6, v7);
            }
        }
    }
}

// ---------------- per-node softmax + gather + relu + instnorm ----------------
__global__ void aggregate_kernel(const float* __restrict__ bo,
                                 int useskip, float* out_ext)
{
    __shared__ float s_a[8][32];
    __shared__ int   s_s[8][32];
    float* out = out_ext ? out_ext : g_h;
    int tid = threadIdx.x;
    int w = tid >> 5, l = tid & 31;
    int n = blockIdx.x * 8 + w;
    if (n >= NNODES) return;

    int r0 = g_rowptr[n], r1 = g_rowptr[n + 1];

    float mx = -3.402823466e38f;
    for (int i = r0 + l; i < r1; i += 32) mx = fmaxf(mx, g_score[i]);
    #pragma unroll
    for (int o = 16; o > 0; o >>= 1) mx = fmaxf(mx, __shfl_xor_sync(0xffffffffu, mx, o));

    float ss = 0.f;
    for (int i = r0 + l; i < r1; i += 32) ss += __expf(g_score[i] - mx);
    #pragma unroll
    for (int o = 16; o > 0; o >>= 1) ss += __shfl_xor_sync(0xffffffffu, ss, o);
    float inv = 1.f / (ss + 1e-16f);

    float acc0 = 0.f, acc1 = 0.f;
    for (int c = r0; c < r1; c += 32) {
        int i = c + l;
        if (i < r1) {
            s_a[w][l] = __expf(g_score[i] - mx) * inv;
            s_s[w][l] = g_esrc[i];
        }
        __syncwarp();
        int cnt = r1 - c; if (cnt > 32) cnt = 32;
        for (int j = 0; j < cnt; j++) {
            float a = s_a[w][j];
            const float* xs = g_xl + (size_t)s_s[w][j] * 64;
            acc0 += a * xs[l];
            acc1 += a * xs[l + 32];
        }
        __syncwarp();
    }

    float v0 = acc0 + bo[l];
    float v1 = acc1 + bo[l + 32];
    if (useskip) {
        v0 += g_skip[(size_t)n * 64 + l];
        v1 += g_skip[(size_t)n * 64 + l + 32];
    }
    v0 = fmaxf(v0, 0.f);
    v1 = fmaxf(v1, 0.f);

    float t = v0 + v1;
    #pragma unroll
    for (int o = 16; o > 0; o >>= 1) t += __shfl_xor_sync(0xffffffffu, t, o);
    float mu = t * (1.f / 64.f);
    float d0 = v0 - mu, d1 = v1 - mu;
    float q = d0 * d0 + d1 * d1;
    #pragma unroll
    for (int o = 16; o > 0; o >>= 1) q += __shfl_xor_sync(0xffffffffu, q, o);
    float sc = rsqrtf(q * (1.f / 64.f) + EPS_IN);

    out[(size_t)n * 64 + l]      = d0 * sc;
    out[(size_t)n * 64 + l + 32] = d1 * sc;
}

// ---------------- launch ----------------
extern "C" void kernel_launch(void* const* d_in, const int* in_sizes, int n_in,
                              void* d_out, int out_size) {
    const float* x     = (const float*)d_in[0];
    const void*  ei    = d_in[1];
    const float* ea    = (const float*)d_in[2];
    const float* Wl1   = (const float*)d_in[3];
    const float* bl1   = (const float*)d_in[4];
    const float* Wr1   = (const float*)d_in[5];
    const float* br1   = (const float*)d_in[6];
    const float* We1   = (const float*)d_in[7];
    const float* att1  = (const float*)d_in[8];
    const float* bo1   = (const float*)d_in[9];
    const float* Wl2   = (const float*)d_in[10];
    const float* bl2   = (const float*)d_in[11];
    const float* Wr2   = (const float*)d_in[12];
    const float* br2   = (const float*)d_in[13];
    const float* We2   = (const float*)d_in[14];
    const float* att2  = (const float*)d_in[15];
    const float* bo2   = (const float*)d_in[16];
    const float* Wskip = (const float*)d_in[17];
    const float* bskip = (const float*)d_in[18];
    float* out = (float*)d_out;

    cudaFuncSetAttribute(gemm_kernel<0>, cudaFuncAttributeMaxDynamicSharedMemorySize, SMEM_BYTES);
    cudaFuncSetAttribute(gemm_kernel<1>, cudaFuncAttributeMaxDynamicSharedMemorySize, SMEM_BYTES);

    const int EB = (NEDGES + 255) / 256;
    const int NB = (NNODES + 255) / 256;
    const int NT = (NNODES + 127) / 128;   // 782 node tiles
    const int ET = NEDGES / 128;           // 12500 edge tiles (exact)

    detect_kernel<<<1, 32>>>((const int*)ei);
    convert_kernel<<<EB, 256>>>(ei);
    zero_deg_kernel<<<NB, 256>>>();
    count_kernel<<<EB, 256>>>();
    scan_kernel<<<1, 1024>>>();
    place_kernel<<<EB, 256>>>();

    // ----- layer 1 -----
    gemm_kernel<0><<<NT, 256, SMEM_BYTES>>>(x, Wl1, bl1, nullptr, 0, 0, NNODES);      // g_xl
    gemm_kernel<0><<<NT, 256, SMEM_BYTES>>>(x, Wr1, br1, nullptr, 0, 1, NNODES);      // g_xr
    gemm_kernel<0><<<NT, 256, SMEM_BYTES>>>(x, Wskip, bskip, nullptr, 0, 2, NNODES);  // g_skip
    gemm_kernel<1><<<ET, 256, SMEM_BYTES>>>(ea, We1, att1, nullptr, 0, 3, NEDGES);    // g_score
    aggregate_kernel<<<(NNODES + 7) / 8, 256>>>(bo1, 0, nullptr);                     // -> g_h

    // ----- layer 2 -----
    gemm_kernel<0><<<NT, 256, SMEM_BYTES>>>(nullptr, Wl2, bl2, nullptr, 1, 0, NNODES);
    gemm_kernel<0><<<NT, 256, SMEM_BYTES>>>(nullptr, Wr2, br2, nullptr, 1, 1, NNODES);
    gemm_kernel<1><<<ET, 256, SMEM_BYTES>>>(ea, We2, att2, nullptr, 0, 3, NEDGES);
    aggregate_kernel<<<(NNODES + 7) / 8, 256>>>(bo2, 1, out);                         // -> d_out
}